// round 5
// baseline (speedup 1.0000x reference)
#include <cuda_runtime.h>

// LatentLinearModel: r[i] = dot(U[users[i]], V[jokes[i]]) + a[users[i]] + b[jokes[i]] + g
// B = 1048576, K = 64.
//
// Round 5: persistent grid-stride blocks + cross-iteration index prefetch.
// The one-shot version pays a serial index-load (~300-600 cyc) before any U
// gather can issue, per tile; that dead time matches the gap from 61% to
// ~saturation. Here each iteration's indices were LDG'd during the PREVIOUS
// iteration, so cp.async gathers issue immediately at loop top.
// cp.async keeps in-flight bytes in smem (regs ~50, 6 blocks/SM).

#define TPR   16                    // threads per row
#define RPG   4                     // rows per 16-lane group per tile
#define BLOCK 256
#define GROUPS (BLOCK / TPR)        // 16
#define RPB   (GROUPS * RPG)        // 64 rows per tile

__device__ __forceinline__ void cp_async16(void* smem, const void* gmem) {
    unsigned s = (unsigned)__cvta_generic_to_shared(smem);
    asm volatile("cp.async.cg.shared.global [%0], [%1], 16;" :: "r"(s), "l"(gmem));
}

__global__ void __launch_bounds__(BLOCK)
latent_linear_kernel(const int* __restrict__ users,
                     const int* __restrict__ jokes,
                     const float4* __restrict__ U4,
                     const float4* __restrict__ V4,
                     const float* __restrict__ a,
                     const float* __restrict__ b,
                     const float* __restrict__ g,
                     float* __restrict__ out,
                     int B, int num_tiles) {
    __shared__ float4 sU[RPB][TPR];   // 16 KB
    __shared__ float4 sV[RPB][TPR];   // 16 KB

    int lane  = threadIdx.x & (TPR - 1);
    int group = threadIdx.x >> 4;
    int lrow0 = group * RPG;

    float gg = __ldg(&g[0]);

    int stride = gridDim.x;
    int t = blockIdx.x;
    if (t >= num_tiles) return;

    // ---- Prefetch indices for the first tile ----
    int4 ui, ji;
    {
        int row0 = t * RPB + lrow0;
        ui = __ldg((const int4*)(users + row0));
        ji = __ldg((const int4*)(jokes + row0));
    }

    for (; t < num_tiles; t += stride) {
        int row0 = t * RPB + lrow0;
        int us[RPG] = {ui.x, ui.y, ui.z, ui.w};
        int js[RPG] = {ji.x, ji.y, ji.z, ji.w};

        // ---- Issue all 8 gathers immediately (indices already resident) ----
        // U first: U is the DRAM stream, get its requests queued earliest.
#pragma unroll
        for (int r = 0; r < RPG; r++)
            cp_async16(&sU[lrow0 + r][lane], &U4[(size_t)us[r] * 16 + lane]);
#pragma unroll
        for (int r = 0; r < RPG; r++)
            cp_async16(&sV[lrow0 + r][lane], &V4[(size_t)js[r] * 16 + lane]);
        asm volatile("cp.async.commit_group;");

        // ---- Prefetch NEXT tile's indices (consumed next iteration) ----
        int tn = t + stride;
        if (tn < num_tiles) {
            int nrow0 = tn * RPB + lrow0;
            ui = __ldg((const int4*)(users + nrow0));
            ji = __ldg((const int4*)(jokes + nrow0));
        }

        // Bias loads fly concurrently with the gathers (lane 0 only; L2-resident).
        float bias[RPG];
        if (lane == 0) {
#pragma unroll
            for (int r = 0; r < RPG; r++)
                bias[r] = __ldg(&a[us[r]]) + __ldg(&b[js[r]]);
        }

        asm volatile("cp.async.wait_group 0;" ::: "memory");

        // ---- Dot + 16-lane reduction per row ----
#pragma unroll
        for (int r = 0; r < RPG; r++) {
            float4 uu = sU[lrow0 + r][lane];
            float4 vv = sV[lrow0 + r][lane];
            float d = uu.x * vv.x + uu.y * vv.y + uu.z * vv.z + uu.w * vv.w;
            d += __shfl_xor_sync(0xffffffffu, d, 8);
            d += __shfl_xor_sync(0xffffffffu, d, 4);
            d += __shfl_xor_sync(0xffffffffu, d, 2);
            d += __shfl_xor_sync(0xffffffffu, d, 1);
            if (lane == 0) {
                int row = row0 + r;
                if (row < B) out[row] = d + bias[r] + gg;
            }
        }
        // No __syncthreads needed: each thread only ever touches its own smem
        // slots, and wait_group 0 orders its own cp.asyncs.
    }
}

extern "C" void kernel_launch(void* const* d_in, const int* in_sizes, int n_in,
                              void* d_out, int out_size) {
    // metadata order: users, jokes, U, V, a, b, g
    const int*    users = (const int*)d_in[0];
    const int*    jokes = (const int*)d_in[1];
    const float4* U4    = (const float4*)d_in[2];
    const float4* V4    = (const float4*)d_in[3];
    const float*  a     = (const float*)d_in[4];
    const float*  b     = (const float*)d_in[5];
    const float*  g     = (const float*)d_in[6];
    float* out = (float*)d_out;

    int B = in_sizes[0];
    int num_tiles = (B + RPB - 1) / RPB;

    int sms = 148;
    cudaDeviceGetAttribute(&sms, cudaDevAttrMultiProcessorCount, 0);

    int grid = sms * 6;               // 6 blocks/SM resident (smem-bound)
    if (grid > num_tiles) grid = num_tiles;

    latent_linear_kernel<<<grid, BLOCK>>>(users, jokes, U4, V4, a, b, g, out,
                                          B, num_tiles);
}